// round 9
// baseline (speedup 1.0000x reference)
#include <cuda_runtime.h>
#include <cuda_fp16.h>
#include <cstdint>

// ---------------------------------------------------------------------------
// Fused sparse-conv block, single-pass fp16 (x and W fp16, fp32 acc).
// R9: M=256 x N=64 mega-tile, 8 warps of 64x32, 1 CTA/SM, 4-stage
//     single-barrier cp.async ring (40KB/stage, 188KB smem total).
//     Rationale: R8 was per-tap-overhead bound (2400cyc/tap vs 900 tensor);
//     doubling tap work per warp amortizes barrier+LDSM ramp.
// ---------------------------------------------------------------------------

typedef __half fp16;
#define N_CH 64
#define MAXP 250048

__device__ fp16 g_x16[(size_t)MAXP * N_CH];   // feats fp16
__device__ fp16 g_a16[(size_t)MAXP * N_CH];   // activation ping
__device__ fp16 g_b16[(size_t)MAXP * N_CH];   // activation pong
__device__ fp16 g_wh[4 * 27 * 64 * 64];

#define TM 256                          // CTA M tile
// ---- smem layout. 128B row pitch + XOR-16B-chunk swizzle (conflict-free).
#define OFF_BIAS  0                     // 64 floats
#define OFF_NBS   256                   // 256*27 ints = 27648 -> 27904
#define OFF_BUF   28672                 // 1024-aligned
#define A_OFF     0                     // 256 rows * 128B = 32768
#define B_OFF     32768                 // 64 rows * 128B = 8192
#define STAGE_SZ  40960
#define N_STAGE   4
#define SMEM_TOTAL (OFF_BUF + N_STAGE * STAGE_SZ)   // 192512 -> 1 CTA/SM

// ---------------- PTX helpers ----------------
__device__ __forceinline__ void cp16b(void* dst, const void* src) {
    uint32_t d;
    asm("{ .reg .u64 t; cvta.to.shared.u64 t, %1; cvt.u32.u64 %0, t; }" : "=r"(d) : "l"(dst));
    asm volatile("cp.async.ca.shared.global [%0], [%1], 16;" :: "r"(d), "l"(src));
}
__device__ __forceinline__ void zero16(void* dst) {
    *(float4*)dst = make_float4(0.f, 0.f, 0.f, 0.f);
}
#define CP_COMMIT() asm volatile("cp.async.commit_group;" ::: "memory")
#define CP_WAIT2()  asm volatile("cp.async.wait_group 2;" ::: "memory")
#define CP_WAIT0()  asm volatile("cp.async.wait_group 0;" ::: "memory")

__device__ __forceinline__ void ldsm4(uint32_t* r, uint32_t addr) {
    asm volatile("ldmatrix.sync.aligned.m8n8.x4.shared.b16 {%0,%1,%2,%3}, [%4];"
                 : "=r"(r[0]), "=r"(r[1]), "=r"(r[2]), "=r"(r[3]) : "r"(addr));
}
__device__ __forceinline__ void mma_fp16(float* c, const uint32_t* a, const uint32_t* b) {
    asm volatile(
        "mma.sync.aligned.m16n8k16.row.col.f32.f16.f16.f32 "
        "{%0,%1,%2,%3}, {%4,%5,%6,%7}, {%8,%9}, {%0,%1,%2,%3};"
        : "+f"(c[0]), "+f"(c[1]), "+f"(c[2]), "+f"(c[3])
        : "r"(a[0]), "r"(a[1]), "r"(a[2]), "r"(a[3]), "r"(b[0]), "r"(b[1]));
}

// ---------------- prep kernels ----------------
__global__ void prep_weights(const float* __restrict__ W0, const float* __restrict__ W1,
                             const float* __restrict__ W2, const float* __restrict__ W3,
                             fp16* __restrict__ wh) {
    int layer = blockIdx.y;
    int i = blockIdx.x * 256 + threadIdx.x;          // over 27*64*64
    if (i >= 27 * 4096) return;
    const float* W = (layer == 0) ? W0 : (layer == 1) ? W1 : (layer == 2) ? W2 : W3;
    int k = i >> 12, n = (i >> 6) & 63, kk = i & 63;
    float w = W[((size_t)k * 64 + kk) * 64 + n];     // store [k][n][kk] (B col-major)
    wh[(size_t)layer * 27 * 4096 + i] = __float2half(w);
}

__global__ void prep_feats(const float* __restrict__ f, fp16* __restrict__ x16, int n) {
    int i = blockIdx.x * 256 + threadIdx.x;
    if (i >= n) return;
    x16[i] = __float2half(f[i]);
}

// ---------------- main conv kernel ----------------
// MODE 0: h = relu(acc+b)            -> fp16 out
// MODE 1: h = (acc+b)*beta + gamma   -> fp16 out  (extra = cond [P,128])
// MODE 3: h = relu(acc+b) + extra    -> fp32 out  (extra = feats [P,64])
template <int MODE>
__global__ __launch_bounds__(256, 1) void conv_mma(
    const fp16* __restrict__ x,
    const int*  __restrict__ nbr,
    const fp16* __restrict__ wh,
    const float* __restrict__ bias, const float* __restrict__ extra,
    float* __restrict__ outf, fp16* __restrict__ out16,
    int P)
{
    extern __shared__ char smem[];
    const uint32_t sb = (uint32_t)__cvta_generic_to_shared(smem);
    const int tid  = threadIdx.x;
    const int wid  = tid >> 5;
    const int lane = tid & 31;
    const int wy   = wid >> 1;        // 0..3 : 64-row slab
    const int wx   = wid & 1;         // 0..1 : 32-col half
    const int rA   = lane >> 2;       // 0..7
    const int cq   = lane & 3;        // 0..3
    const int p0   = blockIdx.x * TM;

    int*   nbs     = (int*)(smem + OFF_NBS);
    float* bias_sm = (float*)(smem + OFF_BIAS);

    if (tid < 64) bias_sm[tid] = bias[tid];
    for (int t = tid; t < TM * 27; t += 256) {
        int row = t / 27, p = p0 + row;
        nbs[t] = (p < P) ? nbr[(size_t)p * 27 + (t - row * 27)] : -1;
    }
    __syncthreads();

    auto gather = [&](int k, int stg) {
        char* base = smem + OFF_BUF + stg * STAGE_SZ;
        // A: 256 rows x 8 chunks = 2048 chunks
        #pragma unroll
        for (int it = 0; it < 8; ++it) {
            int task = it * 256 + tid;
            int row  = task >> 3;
            int c    = task & 7;
            int n    = nbs[row * 27 + k];
            char* dst = base + A_OFF + row * 128 + ((c ^ (row & 7)) << 4);
            if (n >= 0)
                cp16b(dst, x + (size_t)n * 64 + c * 8);
            else
                zero16(dst);
        }
        // B: 64 rows x 8 chunks = 512 chunks
        const fp16* wb = wh + (size_t)k * 4096;
        #pragma unroll
        for (int it = 0; it < 2; ++it) {
            int task = it * 256 + tid;
            int row  = task >> 3;
            int c    = task & 7;
            char* dst = base + B_OFF + row * 128 + ((c ^ (row & 7)) << 4);
            cp16b(dst, wb + (size_t)row * 64 + c * 8);
        }
        CP_COMMIT();
    };

    gather(0, 0);
    gather(1, 1);
    gather(2, 2);

    float acc[4][4][4];               // [m-tile][n-group][frag]
    #pragma unroll
    for (int t = 0; t < 4; ++t)
        #pragma unroll
        for (int j = 0; j < 4; ++j)
            #pragma unroll
            for (int q = 0; q < 4; ++q) acc[t][j][q] = 0.f;

    // ldmatrix lane->address mapping
    const int mm = lane >> 3;         // matrix index 0..3
    const int r8 = lane & 7;
    const int arow0 = wy * 64 + (mm & 1) * 8 + r8;       // tile t adds t*16
    const int akc   = mm >> 1;
    const int brow0 = wx * 32 + (mm >> 1) * 8 + r8;      // pair q adds q*16
    const int bkc   = mm & 1;

    for (int k = 0; k < 27; ++k) {
        const int s = k & 3;
        if (k < 25) CP_WAIT2(); else CP_WAIT0();
        __syncthreads();   // single barrier per tap (4-stage ring)

        const uint32_t stg = sb + OFF_BUF + s * STAGE_SZ;

        #pragma unroll
        for (int ks = 0; ks < 4; ++ks) {
            const int ca = ks * 2 + akc;
            const int cb = ks * 2 + bkc;

            uint32_t a[4][4];
            #pragma unroll
            for (int t = 0; t < 4; ++t) {
                const int row = arow0 + t * 16;
                const uint32_t off = (uint32_t)(row * 128 + (((uint32_t)ca ^ (row & 7)) << 4));
                ldsm4(a[t], stg + A_OFF + off);
            }
            uint32_t b[2][4];
            #pragma unroll
            for (int q = 0; q < 2; ++q) {
                const int row = brow0 + q * 16;
                const uint32_t off = (uint32_t)(row * 128 + (((uint32_t)cb ^ (row & 7)) << 4));
                ldsm4(b[q], stg + B_OFF + off);
            }
            #pragma unroll
            for (int t = 0; t < 4; ++t)
                #pragma unroll
                for (int j = 0; j < 4; ++j)
                    mma_fp16(acc[t][j], a[t], &b[j >> 1][(j & 1) * 2]);
        }
        // gather writes stage (k+3)%4 == (k-1)%4; its readers (tap k-1)
        // retired before this tap's barrier.
        if (k + 3 < 27) gather(k + 3, (k + 3) & 3);
    }

    // ---------------- epilogue ----------------
    #pragma unroll
    for (int t = 0; t < 4; ++t) {
        #pragma unroll
        for (int half = 0; half < 2; ++half) {
            const int p = p0 + wy * 64 + t * 16 + rA + half * 8;
            if (p >= P) continue;
            #pragma unroll
            for (int j = 0; j < 4; ++j) {
                const int col = wx * 32 + j * 8 + cq * 2;
                float v0 = acc[t][j][half * 2 + 0] + bias_sm[col];
                float v1 = acc[t][j][half * 2 + 1] + bias_sm[col + 1];
                if (MODE == 0) {
                    v0 = fmaxf(v0, 0.f); v1 = fmaxf(v1, 0.f);
                } else if (MODE == 1) {
                    float2 be = *(const float2*)(extra + (size_t)p * 128 + col);
                    float2 ga = *(const float2*)(extra + (size_t)p * 128 + 64 + col);
                    v0 = v0 * be.x + ga.x;
                    v1 = v1 * be.y + ga.y;
                } else { // MODE 3
                    float2 rs = *(const float2*)(extra + (size_t)p * 64 + col);
                    v0 = fmaxf(v0, 0.f) + rs.x;
                    v1 = fmaxf(v1, 0.f) + rs.y;
                }
                if (MODE == 3) {
                    *(float2*)(outf + (size_t)p * 64 + col) = make_float2(v0, v1);
                } else {
                    __half2 hv = __floats2half2_rn(v0, v1);
                    *(__half2*)(out16 + (size_t)p * 64 + col) = hv;
                }
            }
        }
    }
}

// ---------------- launch ----------------
extern "C" void kernel_launch(void* const* d_in, const int* in_sizes, int n_in,
                              void* d_out, int out_size)
{
    const float* feats = (const float*)d_in[0];
    const float* cond  = (const float*)d_in[1];
    const float* W1a   = (const float*)d_in[2];
    const float* b1a   = (const float*)d_in[3];
    const float* W1b   = (const float*)d_in[4];
    const float* b1b   = (const float*)d_in[5];
    const float* W2a   = (const float*)d_in[6];
    const float* b2a   = (const float*)d_in[7];
    const float* W2b   = (const float*)d_in[8];
    const float* b2b   = (const float*)d_in[9];
    const int*   nbr   = (const int*)d_in[10];

    int P = in_sizes[0] / N_CH;
    float* out = (float*)d_out;

    fp16 *x16, *a16, *b16, *wh;
    cudaGetSymbolAddress((void**)&x16, g_x16);
    cudaGetSymbolAddress((void**)&a16, g_a16);
    cudaGetSymbolAddress((void**)&b16, g_b16);
    cudaGetSymbolAddress((void**)&wh,  g_wh);

    cudaFuncSetAttribute(conv_mma<0>, cudaFuncAttributeMaxDynamicSharedMemorySize, SMEM_TOTAL);
    cudaFuncSetAttribute(conv_mma<1>, cudaFuncAttributeMaxDynamicSharedMemorySize, SMEM_TOTAL);
    cudaFuncSetAttribute(conv_mma<3>, cudaFuncAttributeMaxDynamicSharedMemorySize, SMEM_TOTAL);

    {
        dim3 g((27 * 4096 + 255) / 256, 4);
        prep_weights<<<g, 256>>>(W1a, W1b, W2a, W2b, wh);
    }
    prep_feats<<<(P * N_CH + 255) / 256, 256>>>(feats, x16, P * N_CH);

    const size_t LW = (size_t)27 * 4096;
    int grid = (P + TM - 1) / TM;
    conv_mma<0><<<grid, 256, SMEM_TOTAL>>>(x16, nbr, wh + 0 * LW,
                                           b1a, nullptr, nullptr, a16, P);
    conv_mma<1><<<grid, 256, SMEM_TOTAL>>>(a16, nbr, wh + 1 * LW,
                                           b1b, cond, nullptr, b16, P);
    conv_mma<0><<<grid, 256, SMEM_TOTAL>>>(b16, nbr, wh + 2 * LW,
                                           b2a, nullptr, nullptr, a16, P);
    conv_mma<3><<<grid, 256, SMEM_TOTAL>>>(a16, nbr, wh + 3 * LW,
                                           b2b, feats, out, nullptr, P);
}

// round 10
// speedup vs baseline: 1.0926x; 1.0926x over previous
#include <cuda_runtime.h>
#include <cuda_fp16.h>
#include <cstdint>

// ---------------------------------------------------------------------------
// Fused sparse-conv block, single-pass fp16 (x and W fp16, fp32 acc).
// R10 (base = R8, the 947us kernel; R9 mega-tile reverted):
//  - B (weights) loaded per-tap directly into registers via frag-ordered
//    LDG.128 (L1/L2-hot, shared across CTAs) -> no B staging, no B-LDSM.
//  - A-only 16KB stages; 6-stage ring in the same 112640B 2-CTA footprint.
//  - 2-tap epochs: ONE __syncthreads per 2 taps (14 barriers vs 27).
// CTA tile: M=128 x N=64, 8 warps (32x32 tiles), 2 CTAs/SM.
// ---------------------------------------------------------------------------

typedef __half fp16;
#define N_CH 64
#define MAXP 250048

__device__ fp16  g_x16[(size_t)MAXP * N_CH];   // feats fp16
__device__ fp16  g_a16[(size_t)MAXP * N_CH];   // activation ping
__device__ fp16  g_b16[(size_t)MAXP * N_CH];   // activation pong
__device__ uint4 g_wf[4 * 27 * 16 * 32];       // frag-ordered weights

// ---- smem layout. 128B row pitch + XOR-16B-chunk swizzle (conflict-free).
#define OFF_BIAS  0                    // 64 floats
#define OFF_NBS   256                  // 128*27 ints = 13824 -> 14080
#define OFF_BUF   14336
#define STAGE_SZ  16384                // A only: 128 rows * 128B
#define N_STAGE   6
#define SMEM_TOTAL (OFF_BUF + N_STAGE * STAGE_SZ)   // 112640 -> 2 CTAs/SM

// ---------------- PTX helpers ----------------
__device__ __forceinline__ void cp16b(void* dst, const void* src) {
    uint32_t d;
    asm("{ .reg .u64 t; cvta.to.shared.u64 t, %1; cvt.u32.u64 %0, t; }" : "=r"(d) : "l"(dst));
    asm volatile("cp.async.ca.shared.global [%0], [%1], 16;" :: "r"(d), "l"(src));
}
__device__ __forceinline__ void zero16(void* dst) {
    *(float4*)dst = make_float4(0.f, 0.f, 0.f, 0.f);
}
#define CP_COMMIT() asm volatile("cp.async.commit_group;" ::: "memory")
#define CP_WAIT2()  asm volatile("cp.async.wait_group 2;" ::: "memory")
#define CP_WAIT1()  asm volatile("cp.async.wait_group 1;" ::: "memory")
#define CP_WAIT0()  asm volatile("cp.async.wait_group 0;" ::: "memory")

__device__ __forceinline__ void ldsm4(uint32_t* r, uint32_t addr) {
    asm volatile("ldmatrix.sync.aligned.m8n8.x4.shared.b16 {%0,%1,%2,%3}, [%4];"
                 : "=r"(r[0]), "=r"(r[1]), "=r"(r[2]), "=r"(r[3]) : "r"(addr));
}
__device__ __forceinline__ void mma_fp16(float* c, const uint32_t* a,
                                         uint32_t b0, uint32_t b1) {
    asm volatile(
        "mma.sync.aligned.m16n8k16.row.col.f32.f16.f16.f32 "
        "{%0,%1,%2,%3}, {%4,%5,%6,%7}, {%8,%9}, {%0,%1,%2,%3};"
        : "+f"(c[0]), "+f"(c[1]), "+f"(c[2]), "+f"(c[3])
        : "r"(a[0]), "r"(a[1]), "r"(a[2]), "r"(a[3]), "r"(b0), "r"(b1));
}

// ---------------- prep kernels ----------------
// Frag-ordered weights: index = ((layer*27+k)*16 + wx*8 + kspair*4 + g)*32 + lane.
// Lane's uint4 = B-frags for n = wx*32+g*8+(lane>>2):
//   .x: kk = 32*kspair +    2*(lane&3) + {0,1}   (b0 of ks=2*kspair)
//   .y: kk = 32*kspair + 8 + ...                 (b1 of ks=2*kspair)
//   .z: kk = 32*kspair +16 + ...                 (b0 of ks=2*kspair+1)
//   .w: kk = 32*kspair +24 + ...                 (b1 of ks=2*kspair+1)
__global__ void prep_weights(const float* __restrict__ W0, const float* __restrict__ W1,
                             const float* __restrict__ W2, const float* __restrict__ W3,
                             uint4* __restrict__ wf) {
    int idx = blockIdx.x * 256 + threadIdx.x;    // over 4*27*16*32 = 55296
    if (idx >= 4 * 27 * 16 * 32) return;
    int lane  = idx & 31;
    int blk   = (idx >> 5) & 15;
    int k     = (idx >> 9) % 27;
    int layer = idx / (27 * 512);
    int wx = blk >> 3, kspair = (blk >> 2) & 1, g = blk & 3;
    int n   = wx * 32 + g * 8 + (lane >> 2);
    int kk0 = kspair * 32 + 2 * (lane & 3);
    const float* W = (layer == 0) ? W0 : (layer == 1) ? W1 : (layer == 2) ? W2 : W3;
    auto pack = [&](int kk) -> uint32_t {
        __half h0 = __float2half(W[((size_t)k * 64 + kk) * 64 + n]);
        __half h1 = __float2half(W[((size_t)k * 64 + kk + 1) * 64 + n]);
        return (uint32_t)__half_as_ushort(h0) | ((uint32_t)__half_as_ushort(h1) << 16);
    };
    uint4 v;
    v.x = pack(kk0); v.y = pack(kk0 + 8); v.z = pack(kk0 + 16); v.w = pack(kk0 + 24);
    wf[idx] = v;
}

__global__ void prep_feats(const float* __restrict__ f, fp16* __restrict__ x16, int n) {
    int i = blockIdx.x * 256 + threadIdx.x;
    if (i >= n) return;
    x16[i] = __float2half(f[i]);
}

// ---------------- main conv kernel ----------------
// MODE 0: h = relu(acc+b)            -> fp16 out
// MODE 1: h = (acc+b)*beta + gamma   -> fp16 out  (extra = cond [P,128])
// MODE 3: h = relu(acc+b) + extra    -> fp32 out  (extra = feats [P,64])
template <int MODE>
__global__ __launch_bounds__(256, 2) void conv_mma(
    const fp16* __restrict__ x,
    const int*  __restrict__ nbr,
    const uint4* __restrict__ wf,     // frag-ordered weights for this layer
    const float* __restrict__ bias, const float* __restrict__ extra,
    float* __restrict__ outf, fp16* __restrict__ out16,
    int P)
{
    extern __shared__ char smem[];
    const uint32_t sb = (uint32_t)__cvta_generic_to_shared(smem);
    const int tid  = threadIdx.x;
    const int wid  = tid >> 5;
    const int lane = tid & 31;
    const int wy   = wid >> 1;        // 0..3 : 32-row slab
    const int wx   = wid & 1;         // 0..1 : 32-col half
    const int rA   = lane >> 2;       // 0..7
    const int cq   = lane & 3;        // 0..3
    const int p0   = blockIdx.x * 128;

    int*   nbs     = (int*)(smem + OFF_NBS);
    float* bias_sm = (float*)(smem + OFF_BIAS);

    if (tid < 64) bias_sm[tid] = bias[tid];
    for (int t = tid; t < 128 * 27; t += 256) {
        int row = t / 27, p = p0 + row;
        nbs[t] = (p < P) ? nbr[(size_t)p * 27 + (t - row * 27)] : -1;
    }
    __syncthreads();

    auto gather = [&](int k, int stg) {
        char* base = smem + OFF_BUF + stg * STAGE_SZ;
        #pragma unroll
        for (int it = 0; it < 4; ++it) {      // A: 128 rows x 8 chunks
            int task = it * 256 + tid;
            int row  = task >> 3;
            int c    = task & 7;
            int n    = nbs[row * 27 + k];
            char* dst = base + row * 128 + ((c ^ (row & 7)) << 4);
            if (n >= 0)
                cp16b(dst, x + (size_t)n * 64 + c * 8);
            else
                zero16(dst);
        }
        CP_COMMIT();
    };

    gather(0, 0); gather(1, 1); gather(2, 2); gather(3, 3);

    float acc[2][4][4];               // [m-tile][n-group][frag]
    #pragma unroll
    for (int t = 0; t < 2; ++t)
        #pragma unroll
        for (int j = 0; j < 4; ++j)
            #pragma unroll
            for (int q = 0; q < 4; ++q) acc[t][j][q] = 0.f;

    // ldmatrix A lane->address mapping
    const int mm = lane >> 3;
    const int r8 = lane & 7;
    const int arow0 = wy * 32 + (mm & 1) * 8 + r8;   // tile t adds t*16
    const int akc   = mm >> 1;

    // per-warp frag-ordered weight base (this warp's 8 blocks per tap)
    const uint4* wbase = wf + ((size_t)wx * 8) * 32 + lane;

    auto compute_tap = [&](int k) {
        const uint32_t stg = sb + OFF_BUF + (k % 6) * STAGE_SZ;
        // B: 8 x LDG.128 (frag-ordered, L1/L2-hot)
        uint4 bv[8];
        const uint4* wp = wbase + (size_t)k * 16 * 32;
        #pragma unroll
        for (int i = 0; i < 8; ++i) bv[i] = wp[i * 32];

        #pragma unroll
        for (int ks = 0; ks < 4; ++ks) {
            const int ca = ks * 2 + akc;
            uint32_t a[2][4];
            #pragma unroll
            for (int t = 0; t < 2; ++t) {
                const int row = arow0 + t * 16;
                const uint32_t off = (uint32_t)(row * 128 + (((uint32_t)ca ^ (row & 7)) << 4));
                ldsm4(a[t], stg + off);
            }
            const int kp = ks >> 1, par = ks & 1;
            #pragma unroll
            for (int t = 0; t < 2; ++t)
                #pragma unroll
                for (int j = 0; j < 4; ++j) {
                    const uint4& b = bv[kp * 4 + j];
                    if (par == 0) mma_fp16(acc[t][j], a[t], b.x, b.y);
                    else          mma_fp16(acc[t][j], a[t], b.z, b.w);
                }
        }
    };

    for (int e = 0; e < 14; ++e) {
        const int k0 = 2 * e;
        const int pend = (k0 + 2 < 27) + (k0 + 3 < 27);
        if (pend == 2) CP_WAIT2(); else if (pend == 1) CP_WAIT1(); else CP_WAIT0();
        __syncthreads();   // ONE barrier per 2 taps (6-stage ring)

        // prefetch next-next pair; stages (k0+4)%6,(k0+5)%6 are not readable
        // this epoch or next, and their last readers retired before this barrier
        if (k0 + 4 < 27) gather(k0 + 4, (k0 + 4) % 6);
        if (k0 + 5 < 27) gather(k0 + 5, (k0 + 5) % 6);

        compute_tap(k0);
        if (k0 + 1 < 27) compute_tap(k0 + 1);
    }

    // ---------------- epilogue ----------------
    #pragma unroll
    for (int t = 0; t < 2; ++t) {
        #pragma unroll
        for (int half = 0; half < 2; ++half) {
            const int p = p0 + wy * 32 + t * 16 + rA + half * 8;
            if (p >= P) continue;
            #pragma unroll
            for (int j = 0; j < 4; ++j) {
                const int col = wx * 32 + j * 8 + cq * 2;
                float v0 = acc[t][j][half * 2 + 0] + bias_sm[col];
                float v1 = acc[t][j][half * 2 + 1] + bias_sm[col + 1];
                if (MODE == 0) {
                    v0 = fmaxf(v0, 0.f); v1 = fmaxf(v1, 0.f);
                } else if (MODE == 1) {
                    float2 be = *(const float2*)(extra + (size_t)p * 128 + col);
                    float2 ga = *(const float2*)(extra + (size_t)p * 128 + 64 + col);
                    v0 = v0 * be.x + ga.x;
                    v1 = v1 * be.y + ga.y;
                } else { // MODE 3
                    float2 rs = *(const float2*)(extra + (size_t)p * 64 + col);
                    v0 = fmaxf(v0, 0.f) + rs.x;
                    v1 = fmaxf(v1, 0.f) + rs.y;
                }
                if (MODE == 3) {
                    *(float2*)(outf + (size_t)p * 64 + col) = make_float2(v0, v1);
                } else {
                    __half2 hv = __floats2half2_rn(v0, v1);
                    *(__half2*)(out16 + (size_t)p * 64 + col) = hv;
                }
            }
        }
    }
}

// ---------------- launch ----------------
extern "C" void kernel_launch(void* const* d_in, const int* in_sizes, int n_in,
                              void* d_out, int out_size)
{
    const float* feats = (const float*)d_in[0];
    const float* cond  = (const float*)d_in[1];
    const float* W1a   = (const float*)d_in[2];
    const float* b1a   = (const float*)d_in[3];
    const float* W1b   = (const float*)d_in[4];
    const float* b1b   = (const float*)d_in[5];
    const float* W2a   = (const float*)d_in[6];
    const float* b2a   = (const float*)d_in[7];
    const float* W2b   = (const float*)d_in[8];
    const float* b2b   = (const float*)d_in[9];
    const int*   nbr   = (const int*)d_in[10];

    int P = in_sizes[0] / N_CH;
    float* out = (float*)d_out;

    fp16 *x16, *a16, *b16;
    uint4* wf;
    cudaGetSymbolAddress((void**)&x16, g_x16);
    cudaGetSymbolAddress((void**)&a16, g_a16);
    cudaGetSymbolAddress((void**)&b16, g_b16);
    cudaGetSymbolAddress((void**)&wf,  g_wf);

    cudaFuncSetAttribute(conv_mma<0>, cudaFuncAttributeMaxDynamicSharedMemorySize, SMEM_TOTAL);
    cudaFuncSetAttribute(conv_mma<1>, cudaFuncAttributeMaxDynamicSharedMemorySize, SMEM_TOTAL);
    cudaFuncSetAttribute(conv_mma<3>, cudaFuncAttributeMaxDynamicSharedMemorySize, SMEM_TOTAL);

    prep_weights<<<(4 * 27 * 16 * 32 + 255) / 256, 256>>>(W1a, W1b, W2a, W2b, wf);
    prep_feats<<<(P * N_CH + 255) / 256, 256>>>(feats, x16, P * N_CH);

    const size_t LW = (size_t)27 * 16 * 32;   // uint4 per layer
    int grid = (P + 127) / 128;
    conv_mma<0><<<grid, 256, SMEM_TOTAL>>>(x16, nbr, wf + 0 * LW,
                                           b1a, nullptr, nullptr, a16, P);
    conv_mma<1><<<grid, 256, SMEM_TOTAL>>>(a16, nbr, wf + 1 * LW,
                                           b1b, cond, nullptr, b16, P);
    conv_mma<0><<<grid, 256, SMEM_TOTAL>>>(b16, nbr, wf + 2 * LW,
                                           b2a, nullptr, nullptr, a16, P);
    conv_mma<3><<<grid, 256, SMEM_TOTAL>>>(a16, nbr, wf + 3 * LW,
                                           b2b, feats, out, nullptr, P);
}

// round 11
// speedup vs baseline: 1.3553x; 1.2404x over previous
#include <cuda_runtime.h>
#include <cuda_fp16.h>
#include <cstdint>

// ---------------------------------------------------------------------------
// Fused sparse-conv block, single-pass fp16 (x and W fp16, fp32 acc).
// R11: exploit 1.5% voxel occupancy (bit-exact vs dense R8/R10):
//  - stages zeroed ONCE; per tap cp.async only valid rows (~2/128) and
//    re-zero rows valid 6 taps ago (ring invariant keeps the rest zero)
//  - per-(tap,16-row-group) activity bits -> warps skip ldsm/MMA for dead
//    m-tiles (~78%) and skip B LDG when fully idle (~62%)
//  - base skeleton = R10: frag-ordered B LDG.128, 6-stage ring, 2-tap
//    epochs (14 barriers), 2 CTAs/SM.
// CTA tile: M=128 x N=64, 8 warps (32x32 tiles).
// ---------------------------------------------------------------------------

typedef __half fp16;
#define N_CH 64
#define MAXP 250048

__device__ fp16  g_x16[(size_t)MAXP * N_CH];   // feats fp16
__device__ fp16  g_a16[(size_t)MAXP * N_CH];   // activation ping
__device__ fp16  g_b16[(size_t)MAXP * N_CH];   // activation pong
__device__ uint4 g_wf[4 * 27 * 16 * 32];       // frag-ordered weights

// ---- smem layout. 128B row pitch + XOR-16B-chunk swizzle (conflict-free).
#define OFF_BIAS  0                    // 64 floats = 256
#define OFF_NBS   256                  // 128*27 ints = 13824 -> 14080
#define OFF_G16   14080                // 27*8 activity bytes = 216 -> 14296
#define OFF_BUF   14336
#define STAGE_SZ  16384                // A only: 128 rows * 128B
#define N_STAGE   6
#define SMEM_TOTAL (OFF_BUF + N_STAGE * STAGE_SZ)   // 112640 -> 2 CTAs/SM

// ---------------- PTX helpers ----------------
__device__ __forceinline__ void cp16b(void* dst, const void* src) {
    uint32_t d;
    asm("{ .reg .u64 t; cvta.to.shared.u64 t, %1; cvt.u32.u64 %0, t; }" : "=r"(d) : "l"(dst));
    asm volatile("cp.async.ca.shared.global [%0], [%1], 16;" :: "r"(d), "l"(src));
}
__device__ __forceinline__ void zero16(void* dst) {
    *(float4*)dst = make_float4(0.f, 0.f, 0.f, 0.f);
}
#define CP_COMMIT() asm volatile("cp.async.commit_group;" ::: "memory")
#define CP_WAIT2()  asm volatile("cp.async.wait_group 2;" ::: "memory")
#define CP_WAIT1()  asm volatile("cp.async.wait_group 1;" ::: "memory")
#define CP_WAIT0()  asm volatile("cp.async.wait_group 0;" ::: "memory")

__device__ __forceinline__ void ldsm4(uint32_t* r, uint32_t addr) {
    asm volatile("ldmatrix.sync.aligned.m8n8.x4.shared.b16 {%0,%1,%2,%3}, [%4];"
                 : "=r"(r[0]), "=r"(r[1]), "=r"(r[2]), "=r"(r[3]) : "r"(addr));
}
__device__ __forceinline__ void mma_fp16(float* c, const uint32_t* a,
                                         uint32_t b0, uint32_t b1) {
    asm volatile(
        "mma.sync.aligned.m16n8k16.row.col.f32.f16.f16.f32 "
        "{%0,%1,%2,%3}, {%4,%5,%6,%7}, {%8,%9}, {%0,%1,%2,%3};"
        : "+f"(c[0]), "+f"(c[1]), "+f"(c[2]), "+f"(c[3])
        : "r"(a[0]), "r"(a[1]), "r"(a[2]), "r"(a[3]), "r"(b0), "r"(b1));
}

// ---------------- prep kernels ----------------
// Frag-ordered weights (see R10): lane's uint4 = B frags for
// n = wx*32+g*8+(lane>>2), kk groups per kspair.
__global__ void prep_weights(const float* __restrict__ W0, const float* __restrict__ W1,
                             const float* __restrict__ W2, const float* __restrict__ W3,
                             uint4* __restrict__ wf) {
    int idx = blockIdx.x * 256 + threadIdx.x;    // over 4*27*16*32 = 55296
    if (idx >= 4 * 27 * 16 * 32) return;
    int lane  = idx & 31;
    int blk   = (idx >> 5) & 15;
    int k     = (idx >> 9) % 27;
    int layer = idx / (27 * 512);
    int wx = blk >> 3, kspair = (blk >> 2) & 1, g = blk & 3;
    int n   = wx * 32 + g * 8 + (lane >> 2);
    int kk0 = kspair * 32 + 2 * (lane & 3);
    const float* W = (layer == 0) ? W0 : (layer == 1) ? W1 : (layer == 2) ? W2 : W3;
    auto pack = [&](int kk) -> uint32_t {
        __half h0 = __float2half(W[((size_t)k * 64 + kk) * 64 + n]);
        __half h1 = __float2half(W[((size_t)k * 64 + kk + 1) * 64 + n]);
        return (uint32_t)__half_as_ushort(h0) | ((uint32_t)__half_as_ushort(h1) << 16);
    };
    uint4 v;
    v.x = pack(kk0); v.y = pack(kk0 + 8); v.z = pack(kk0 + 16); v.w = pack(kk0 + 24);
    wf[idx] = v;
}

__global__ void prep_feats(const float* __restrict__ f, fp16* __restrict__ x16, int n) {
    int i = blockIdx.x * 256 + threadIdx.x;
    if (i >= n) return;
    x16[i] = __float2half(f[i]);
}

// ---------------- main conv kernel ----------------
// MODE 0: h = relu(acc+b)            -> fp16 out
// MODE 1: h = (acc+b)*beta + gamma   -> fp16 out  (extra = cond [P,128])
// MODE 3: h = relu(acc+b) + extra    -> fp32 out  (extra = feats [P,64])
template <int MODE>
__global__ __launch_bounds__(256, 2) void conv_mma(
    const fp16* __restrict__ x,
    const int*  __restrict__ nbr,
    const uint4* __restrict__ wf,     // frag-ordered weights for this layer
    const float* __restrict__ bias, const float* __restrict__ extra,
    float* __restrict__ outf, fp16* __restrict__ out16,
    int P)
{
    extern __shared__ char smem[];
    const uint32_t sb = (uint32_t)__cvta_generic_to_shared(smem);
    const int tid  = threadIdx.x;
    const int wid  = tid >> 5;
    const int lane = tid & 31;
    const int wy   = wid >> 1;        // 0..3 : 32-row slab
    const int wx   = wid & 1;         // 0..1 : 32-col half
    const int rA   = lane >> 2;       // 0..7
    const int cq   = lane & 3;        // 0..3
    const int p0   = blockIdx.x * 128;

    int*           nbs     = (int*)(smem + OFF_NBS);
    float*         bias_sm = (float*)(smem + OFF_BIAS);
    unsigned char* g16     = (unsigned char*)(smem + OFF_G16);

    // phase 1: bias + neighbor table
    if (tid < 64) bias_sm[tid] = bias[tid];
    for (int t = tid; t < 128 * 27; t += 256) {
        int row = t / 27, p = p0 + row;
        nbs[t] = (p < P) ? nbr[(size_t)p * 27 + (t - row * 27)] : -1;
    }
    __syncthreads();

    // phase 2: activity bits (27 taps x 8 row-groups) + zero all stages once
    if (tid < 216) {
        int k = tid >> 3, g = tid & 7;
        unsigned char any = 0;
        #pragma unroll
        for (int r = 0; r < 16; ++r)
            any |= (nbs[(g * 16 + r) * 27 + k] >= 0);
        g16[tid] = any;
    }
    for (int i = tid; i < N_STAGE * STAGE_SZ / 16; i += 256)
        zero16(smem + OFF_BUF + i * 16);
    __syncthreads();

    // sparse gather: 2 threads per row; only valid rows cp.async'd, only
    // rows valid 6 taps ago (stage's previous tenant) re-zeroed.
    auto gather = [&](int k, int stg) {
        char* base = smem + OFF_BUF + stg * STAGE_SZ;
        const int row  = tid >> 1;
        const int half = tid & 1;
        const int n = nbs[row * 27 + k];
        char* dst = base + row * 128;
        if (n >= 0) {
            const fp16* src = x + (size_t)n * 64;
            #pragma unroll
            for (int c = 0; c < 4; ++c) {
                int cc = half * 4 + c;
                cp16b(dst + ((cc ^ (row & 7)) << 4), src + cc * 8);
            }
        } else if (k >= 6 && nbs[row * 27 + (k - 6)] >= 0) {
            #pragma unroll
            for (int c = 0; c < 4; ++c) {
                int cc = half * 4 + c;
                zero16(dst + ((cc ^ (row & 7)) << 4));
            }
        }
        CP_COMMIT();
    };

    gather(0, 0); gather(1, 1); gather(2, 2); gather(3, 3);

    float acc[2][4][4];               // [m-tile][n-group][frag]
    #pragma unroll
    for (int t = 0; t < 2; ++t)
        #pragma unroll
        for (int j = 0; j < 4; ++j)
            #pragma unroll
            for (int q = 0; q < 4; ++q) acc[t][j][q] = 0.f;

    // ldmatrix A lane->address mapping
    const int mm = lane >> 3;
    const int r8 = lane & 7;
    const int arow0 = wy * 32 + (mm & 1) * 8 + r8;   // tile t adds t*16
    const int akc   = mm >> 1;

    const uint4* wbase = wf + ((size_t)wx * 8) * 32 + lane;

    auto compute_tap = [&](int k) {
        const bool act0 = g16[k * 8 + wy * 2 + 0] != 0;
        const bool act1 = g16[k * 8 + wy * 2 + 1] != 0;
        if (!act0 && !act1) return;                  // warp idle this tap

        const uint32_t stg = sb + OFF_BUF + (k % 6) * STAGE_SZ;
        uint4 bv[8];
        const uint4* wp = wbase + (size_t)k * 16 * 32;
        #pragma unroll
        for (int i = 0; i < 8; ++i) bv[i] = wp[i * 32];

        #pragma unroll
        for (int ks = 0; ks < 4; ++ks) {
            const int ca = ks * 2 + akc;
            uint32_t a[2][4];
            #pragma unroll
            for (int t = 0; t < 2; ++t) {
                if (t == 0 ? act0 : act1) {
                    const int row = arow0 + t * 16;
                    const uint32_t off =
                        (uint32_t)(row * 128 + (((uint32_t)ca ^ (row & 7)) << 4));
                    ldsm4(a[t], stg + off);
                }
            }
            const int kp = ks >> 1, par = ks & 1;
            #pragma unroll
            for (int t = 0; t < 2; ++t) {
                if (t == 0 ? !act0 : !act1) continue;
                #pragma unroll
                for (int j = 0; j < 4; ++j) {
                    const uint4& b = bv[kp * 4 + j];
                    if (par == 0) mma_fp16(acc[t][j], a[t], b.x, b.y);
                    else          mma_fp16(acc[t][j], a[t], b.z, b.w);
                }
            }
        }
    };

    for (int e = 0; e < 14; ++e) {
        const int k0 = 2 * e;
        const int pend = (k0 + 2 < 27) + (k0 + 3 < 27);
        if (pend == 2) CP_WAIT2(); else if (pend == 1) CP_WAIT1(); else CP_WAIT0();
        __syncthreads();   // one barrier per 2 taps (6-stage ring)

        if (k0 + 4 < 27) gather(k0 + 4, (k0 + 4) % 6);
        if (k0 + 5 < 27) gather(k0 + 5, (k0 + 5) % 6);

        compute_tap(k0);
        if (k0 + 1 < 27) compute_tap(k0 + 1);
    }

    // ---------------- epilogue ----------------
    #pragma unroll
    for (int t = 0; t < 2; ++t) {
        #pragma unroll
        for (int half = 0; half < 2; ++half) {
            const int p = p0 + wy * 32 + t * 16 + rA + half * 8;
            if (p >= P) continue;
            #pragma unroll
            for (int j = 0; j < 4; ++j) {
                const int col = wx * 32 + j * 8 + cq * 2;
                float v0 = acc[t][j][half * 2 + 0] + bias_sm[col];
                float v1 = acc[t][j][half * 2 + 1] + bias_sm[col + 1];
                if (MODE == 0) {
                    v0 = fmaxf(v0, 0.f); v1 = fmaxf(v1, 0.f);
                } else if (MODE == 1) {
                    float2 be = *(const float2*)(extra + (size_t)p * 128 + col);
                    float2 ga = *(const float2*)(extra + (size_t)p * 128 + 64 + col);
                    v0 = v0 * be.x + ga.x;
                    v1 = v1 * be.y + ga.y;
                } else { // MODE 3
                    float2 rs = *(const float2*)(extra + (size_t)p * 64 + col);
                    v0 = fmaxf(v0, 0.f) + rs.x;
                    v1 = fmaxf(v1, 0.f) + rs.y;
                }
                if (MODE == 3) {
                    *(float2*)(outf + (size_t)p * 64 + col) = make_float2(v0, v1);
                } else {
                    __half2 hv = __floats2half2_rn(v0, v1);
                    *(__half2*)(out16 + (size_t)p * 64 + col) = hv;
                }
            }
        }
    }
}

// ---------------- launch ----------------
extern "C" void kernel_launch(void* const* d_in, const int* in_sizes, int n_in,
                              void* d_out, int out_size)
{
    const float* feats = (const float*)d_in[0];
    const float* cond  = (const float*)d_in[1];
    const float* W1a   = (const float*)d_in[2];
    const float* b1a   = (const float*)d_in[3];
    const float* W1b   = (const float*)d_in[4];
    const float* b1b   = (const float*)d_in[5];
    const float* W2a   = (const float*)d_in[6];
    const float* b2a   = (const float*)d_in[7];
    const float* W2b   = (const float*)d_in[8];
    const float* b2b   = (const float*)d_in[9];
    const int*   nbr   = (const int*)d_in[10];

    int P = in_sizes[0] / N_CH;
    float* out = (float*)d_out;

    fp16 *x16, *a16, *b16;
    uint4* wf;
    cudaGetSymbolAddress((void**)&x16, g_x16);
    cudaGetSymbolAddress((void**)&a16, g_a16);
    cudaGetSymbolAddress((void**)&b16, g_b16);
    cudaGetSymbolAddress((void**)&wf,  g_wf);

    cudaFuncSetAttribute(conv_mma<0>, cudaFuncAttributeMaxDynamicSharedMemorySize, SMEM_TOTAL);
    cudaFuncSetAttribute(conv_mma<1>, cudaFuncAttributeMaxDynamicSharedMemorySize, SMEM_TOTAL);
    cudaFuncSetAttribute(conv_mma<3>, cudaFuncAttributeMaxDynamicSharedMemorySize, SMEM_TOTAL);

    prep_weights<<<(4 * 27 * 16 * 32 + 255) / 256, 256>>>(W1a, W1b, W2a, W2b, wf);
    prep_feats<<<(P * N_CH + 255) / 256, 256>>>(feats, x16, P * N_CH);

    const size_t LW = (size_t)27 * 16 * 32;   // uint4 per layer
    int grid = (P + 127) / 128;
    conv_mma<0><<<grid, 256, SMEM_TOTAL>>>(x16, nbr, wf + 0 * LW,
                                           b1a, nullptr, nullptr, a16, P);
    conv_mma<1><<<grid, 256, SMEM_TOTAL>>>(a16, nbr, wf + 1 * LW,
                                           b1b, cond, nullptr, b16, P);
    conv_mma<0><<<grid, 256, SMEM_TOTAL>>>(b16, nbr, wf + 2 * LW,
                                           b2a, nullptr, nullptr, a16, P);
    conv_mma<3><<<grid, 256, SMEM_TOTAL>>>(a16, nbr, wf + 3 * LW,
                                           b2b, feats, out, nullptr, P);
}

// round 12
// speedup vs baseline: 1.4778x; 1.0904x over previous
#include <cuda_runtime.h>
#include <cuda_fp16.h>
#include <cstdint>

// ---------------------------------------------------------------------------
// Fused sparse-conv block, single-pass fp16 (x and W fp16, fp32 acc).
// R12: warp-autonomous sparse mainloop. Each warp iterates ONLY its active
// taps (avg ~11/27) with a private double-buffered smem stage +
// cp.async.wait_group/__syncwarp — NO __syncthreads in the mainloop.
// Base mechanisms from R10/R11: frag-ordered B LDG.128, XOR-swizzled A,
// 16-row-group activity skip, 2 CTAs/SM.
// CTA tile: M=128 x N=64, 8 warps (32x32 tiles).
// ---------------------------------------------------------------------------

typedef __half fp16;
#define N_CH 64
#define MAXP 250048

__device__ fp16  g_x16[(size_t)MAXP * N_CH];   // feats fp16
__device__ fp16  g_a16[(size_t)MAXP * N_CH];   // activation ping
__device__ fp16  g_b16[(size_t)MAXP * N_CH];   // activation pong
__device__ uint4 g_wf[4 * 27 * 16 * 32];       // frag-ordered weights

// ---- smem layout ----
#define OFF_BIAS  0                    // 64 floats = 256
#define OFF_NBS   256                  // 128*27 ints = 13824 -> 14080
#define OFF_G16   14080                // 27*8 activity bytes -> 14296
#define OFF_WBUF  14336                // 8 warps * 2 bufs * 4096B
#define SMEM_TOTAL (OFF_WBUF + 8 * 2 * 4096)   // 79872 -> 2 CTAs/SM

// ---------------- PTX helpers ----------------
__device__ __forceinline__ void cp16b(void* dst, const void* src) {
    uint32_t d;
    asm("{ .reg .u64 t; cvta.to.shared.u64 t, %1; cvt.u32.u64 %0, t; }" : "=r"(d) : "l"(dst));
    asm volatile("cp.async.ca.shared.global [%0], [%1], 16;" :: "r"(d), "l"(src));
}
__device__ __forceinline__ void zero16(void* dst) {
    *(float4*)dst = make_float4(0.f, 0.f, 0.f, 0.f);
}
#define CP_COMMIT() asm volatile("cp.async.commit_group;" ::: "memory")
#define CP_WAIT1()  asm volatile("cp.async.wait_group 1;" ::: "memory")
#define CP_WAIT0()  asm volatile("cp.async.wait_group 0;" ::: "memory")

__device__ __forceinline__ void ldsm4(uint32_t* r, uint32_t addr) {
    asm volatile("ldmatrix.sync.aligned.m8n8.x4.shared.b16 {%0,%1,%2,%3}, [%4];"
                 : "=r"(r[0]), "=r"(r[1]), "=r"(r[2]), "=r"(r[3]) : "r"(addr));
}
__device__ __forceinline__ void mma_fp16(float* c, const uint32_t* a,
                                         uint32_t b0, uint32_t b1) {
    asm volatile(
        "mma.sync.aligned.m16n8k16.row.col.f32.f16.f16.f32 "
        "{%0,%1,%2,%3}, {%4,%5,%6,%7}, {%8,%9}, {%0,%1,%2,%3};"
        : "+f"(c[0]), "+f"(c[1]), "+f"(c[2]), "+f"(c[3])
        : "r"(a[0]), "r"(a[1]), "r"(a[2]), "r"(a[3]), "r"(b0), "r"(b1));
}

// ---------------- prep kernels ----------------
// Frag-ordered weights (see R10): lane's uint4 = B frags for
// n = wx*32+g*8+(lane>>2), kk groups per kspair.
__global__ void prep_weights(const float* __restrict__ W0, const float* __restrict__ W1,
                             const float* __restrict__ W2, const float* __restrict__ W3,
                             uint4* __restrict__ wf) {
    int idx = blockIdx.x * 256 + threadIdx.x;    // over 4*27*16*32 = 55296
    if (idx >= 4 * 27 * 16 * 32) return;
    int lane  = idx & 31;
    int blk   = (idx >> 5) & 15;
    int k     = (idx >> 9) % 27;
    int layer = idx / (27 * 512);
    int wx = blk >> 3, kspair = (blk >> 2) & 1, g = blk & 3;
    int n   = wx * 32 + g * 8 + (lane >> 2);
    int kk0 = kspair * 32 + 2 * (lane & 3);
    const float* W = (layer == 0) ? W0 : (layer == 1) ? W1 : (layer == 2) ? W2 : W3;
    auto pack = [&](int kk) -> uint32_t {
        __half h0 = __float2half(W[((size_t)k * 64 + kk) * 64 + n]);
        __half h1 = __float2half(W[((size_t)k * 64 + kk + 1) * 64 + n]);
        return (uint32_t)__half_as_ushort(h0) | ((uint32_t)__half_as_ushort(h1) << 16);
    };
    uint4 v;
    v.x = pack(kk0); v.y = pack(kk0 + 8); v.z = pack(kk0 + 16); v.w = pack(kk0 + 24);
    wf[idx] = v;
}

__global__ void prep_feats(const float* __restrict__ f, fp16* __restrict__ x16, int n) {
    int i = blockIdx.x * 256 + threadIdx.x;
    if (i >= n) return;
    x16[i] = __float2half(f[i]);
}

// ---------------- main conv kernel ----------------
// MODE 0: h = relu(acc+b)            -> fp16 out
// MODE 1: h = (acc+b)*beta + gamma   -> fp16 out  (extra = cond [P,128])
// MODE 3: h = relu(acc+b) + extra    -> fp32 out  (extra = feats [P,64])
template <int MODE>
__global__ __launch_bounds__(256, 2) void conv_mma(
    const fp16* __restrict__ x,
    const int*  __restrict__ nbr,
    const uint4* __restrict__ wf,
    const float* __restrict__ bias, const float* __restrict__ extra,
    float* __restrict__ outf, fp16* __restrict__ out16,
    int P)
{
    extern __shared__ char smem[];
    const uint32_t sb = (uint32_t)__cvta_generic_to_shared(smem);
    const int tid  = threadIdx.x;
    const int wid  = tid >> 5;
    const int lane = tid & 31;
    const int wy   = wid >> 1;        // 0..3 : 32-row slab
    const int wx   = wid & 1;         // 0..1 : 32-col half
    const int rA   = lane >> 2;       // 0..7
    const int cq   = lane & 3;        // 0..3
    const int p0   = blockIdx.x * 128;

    int*           nbs     = (int*)(smem + OFF_NBS);
    float*         bias_sm = (float*)(smem + OFF_BIAS);
    unsigned char* g16     = (unsigned char*)(smem + OFF_G16);

    // ---- prologue: bias + neighbor table + activity bits (ONE CTA barrier) ----
    if (tid < 64) bias_sm[tid] = bias[tid];
    for (int t = tid; t < 128 * 27; t += 256) {
        int row = t / 27, p = p0 + row;
        nbs[t] = (p < P) ? nbr[(size_t)p * 27 + (t - row * 27)] : -1;
    }
    __syncthreads();
    if (tid < 216) {
        int k = tid >> 3, g = tid & 7;
        unsigned char any = 0;
        #pragma unroll
        for (int r = 0; r < 16; ++r)
            any |= (nbs[(g * 16 + r) * 27 + k] >= 0);
        g16[tid] = any;
    }
    __syncthreads();

    // ---- per-warp active-tap mask (uniform across lanes: same smem reads) ----
    uint32_t wmask = 0;
    #pragma unroll
    for (int k = 0; k < 27; ++k)
        if (g16[k * 8 + wy * 2] | g16[k * 8 + wy * 2 + 1]) wmask |= (1u << k);

    float acc[2][4][4];
    #pragma unroll
    for (int t = 0; t < 2; ++t)
        #pragma unroll
        for (int j = 0; j < 4; ++j)
            #pragma unroll
            for (int q = 0; q < 4; ++q) acc[t][j][q] = 0.f;

    // warp-private staging: stage tap k's 32 rows into buf (8 chunks/lane)
    char* wbuf0 = smem + OFF_WBUF + wid * 8192;
    auto stage = [&](int k, int buf) {
        char* base = wbuf0 + buf * 4096;
        #pragma unroll
        for (int i = 0; i < 8; ++i) {
            int id  = i * 32 + lane;
            int row = id >> 3;
            int c   = id & 7;
            int n   = nbs[(wy * 32 + row) * 27 + k];
            char* dst = base + row * 128 + ((c ^ (row & 7)) << 4);
            if (n >= 0)
                cp16b(dst, x + (size_t)n * 64 + c * 8);
            else
                zero16(dst);
        }
        CP_COMMIT();
    };

    // ldmatrix A mapping (warp-local rows 0..31)
    const int mm = lane >> 3;
    const int r8 = lane & 7;
    const int arow0 = (mm & 1) * 8 + r8;     // tile t adds t*16
    const int akc   = mm >> 1;

    const uint4* wbase = wf + ((size_t)wx * 8) * 32 + lane;

    auto compute = [&](int k, int buf) {
        const bool act0 = g16[k * 8 + wy * 2 + 0] != 0;
        const bool act1 = g16[k * 8 + wy * 2 + 1] != 0;
        const uint32_t stg = sb + OFF_WBUF + (uint32_t)(wid * 8192 + buf * 4096);
        const uint4* wp = wbase + (size_t)k * 16 * 32;

        #pragma unroll
        for (int kp = 0; kp < 2; ++kp) {
            uint4 bv[4];
            #pragma unroll
            for (int i = 0; i < 4; ++i) bv[i] = wp[(kp * 4 + i) * 32];

            #pragma unroll
            for (int par = 0; par < 2; ++par) {
                const int ca = (kp * 2 + par) * 2 + akc;
                uint32_t a[2][4];
                #pragma unroll
                for (int t = 0; t < 2; ++t) {
                    if (t == 0 ? act0 : act1) {
                        const int row = arow0 + t * 16;
                        const uint32_t off =
                            (uint32_t)(row * 128 + (((uint32_t)ca ^ (row & 7)) << 4));
                        ldsm4(a[t], stg + off);
                    }
                }
                #pragma unroll
                for (int t = 0; t < 2; ++t) {
                    if (t == 0 ? !act0 : !act1) continue;
                    #pragma unroll
                    for (int j = 0; j < 4; ++j) {
                        if (par == 0) mma_fp16(acc[t][j], a[t], bv[j].x, bv[j].y);
                        else          mma_fp16(acc[t][j], a[t], bv[j].z, bv[j].w);
                    }
                }
            }
        }
    };

    // ---- warp-autonomous mainloop over active taps (no CTA barriers) ----
    if (wmask) {
        uint32_t m = wmask;
        int k = __ffs(m) - 1; m &= m - 1;
        int buf = 0;
        stage(k, 0);
        while (m) {
            int kn = __ffs(m) - 1; m &= m - 1;
            stage(kn, buf ^ 1);
            CP_WAIT1();
            __syncwarp();
            compute(k, buf);
            k = kn; buf ^= 1;
        }
        CP_WAIT0();
        __syncwarp();
        compute(k, buf);
    }

    // ---------------- epilogue ----------------
    #pragma unroll
    for (int t = 0; t < 2; ++t) {
        #pragma unroll
        for (int half = 0; half < 2; ++half) {
            const int p = p0 + wy * 32 + t * 16 + rA + half * 8;
            if (p >= P) continue;
            #pragma unroll
            for (int j = 0; j < 4; ++j) {
                const int col = wx * 32 + j * 8 + cq * 2;
                float v0 = acc[t][j][half * 2 + 0] + bias_sm[col];
                float v1 = acc[t][j][half * 2 + 1] + bias_sm[col + 1];
                if (MODE == 0) {
                    v0 = fmaxf(v0, 0.f); v1 = fmaxf(v1, 0.f);
                } else if (MODE == 1) {
                    float2 be = *(const float2*)(extra + (size_t)p * 128 + col);
                    float2 ga = *(const float2*)(extra + (size_t)p * 128 + 64 + col);
                    v0 = v0 * be.x + ga.x;
                    v1 = v1 * be.y + ga.y;
                } else { // MODE 3
                    float2 rs = *(const float2*)(extra + (size_t)p * 64 + col);
                    v0 = fmaxf(v0, 0.f) + rs.x;
                    v1 = fmaxf(v1, 0.f) + rs.y;
                }
                if (MODE == 3) {
                    *(float2*)(outf + (size_t)p * 64 + col) = make_float2(v0, v1);
                } else {
                    __half2 hv = __floats2half2_rn(v0, v1);
                    *(__half2*)(out16 + (size_t)p * 64 + col) = hv;
                }
            }
        }
    }
}

// ---------------- launch ----------------
extern "C" void kernel_launch(void* const* d_in, const int* in_sizes, int n_in,
                              void* d_out, int out_size)
{
    const float* feats = (const float*)d_in[0];
    const float* cond  = (const float*)d_in[1];
    const float* W1a   = (const float*)d_in[2];
    const float* b1a   = (const float*)d_in[3];
    const float* W1b   = (const float*)d_in[4];
    const float* b1b   = (const float*)d_in[5];
    const float* W2a   = (const float*)d_in[6];
    const float* b2a   = (const float*)d_in[7];
    const float* W2b   = (const float*)d_in[8];
    const float* b2b   = (const float*)d_in[9];
    const int*   nbr   = (const int*)d_in[10];

    int P = in_sizes[0] / N_CH;
    float* out = (float*)d_out;

    fp16 *x16, *a16, *b16;
    uint4* wf;
    cudaGetSymbolAddress((void**)&x16, g_x16);
    cudaGetSymbolAddress((void**)&a16, g_a16);
    cudaGetSymbolAddress((void**)&b16, g_b16);
    cudaGetSymbolAddress((void**)&wf,  g_wf);

    cudaFuncSetAttribute(conv_mma<0>, cudaFuncAttributeMaxDynamicSharedMemorySize, SMEM_TOTAL);
    cudaFuncSetAttribute(conv_mma<1>, cudaFuncAttributeMaxDynamicSharedMemorySize, SMEM_TOTAL);
    cudaFuncSetAttribute(conv_mma<3>, cudaFuncAttributeMaxDynamicSharedMemorySize, SMEM_TOTAL);

    prep_weights<<<(4 * 27 * 16 * 32 + 255) / 256, 256>>>(W1a, W1b, W2a, W2b, wf);
    prep_feats<<<(P * N_CH + 255) / 256, 256>>>(feats, x16, P * N_CH);

    const size_t LW = (size_t)27 * 16 * 32;   // uint4 per layer
    int grid = (P + 127) / 128;
    conv_mma<0><<<grid, 256, SMEM_TOTAL>>>(x16, nbr, wf + 0 * LW,
                                           b1a, nullptr, nullptr, a16, P);
    conv_mma<1><<<grid, 256, SMEM_TOTAL>>>(a16, nbr, wf + 1 * LW,
                                           b1b, cond, nullptr, b16, P);
    conv_mma<0><<<grid, 256, SMEM_TOTAL>>>(b16, nbr, wf + 2 * LW,
                                           b2a, nullptr, nullptr, a16, P);
    conv_mma<3><<<grid, 256, SMEM_TOTAL>>>(a16, nbr, wf + 3 * LW,
                                           b2b, feats, out, nullptr, P);
}